// round 13
// baseline (speedup 1.0000x reference)
#include <cuda_runtime.h>
#include <cuda_bf16.h>
#include <cuda_fp16.h>
#include <cstdint>

// Problem constants
#define BB    8
#define CC    128
#define HWV   4096       // H*W
#define PJV   1024       // pooled positions
#define C8    16
#define C2    64
#define LG2E  1.44269504f

// Scratch (device globals; no allocation allowed)
__device__ __align__(16) __half         Qf [BB * HWV * C8];   // 1 MB   (pre-scaled by log2e)
__device__ __align__(16) __half         Kf [BB * PJV * C8];   // 256 KB
__device__ __align__(16) __nv_bfloat16  Vg [BB * PJV * C2];   // 1 MB   (bf16: pairs with bf16 P)

// ===================== helpers =============================================
__device__ __forceinline__ uint32_t smem_u32(const void* p) {
    uint32_t a;
    asm("{ .reg .u64 t; cvta.to.shared.u64 t, %1; cvt.u32.u64 %0, t; }" : "=r"(a) : "l"(p));
    return a;
}
#define SWZ(o) ((o) ^ (((o) >> 3) & 0x70))

__device__ __forceinline__ void cp_async16(uint32_t dst, const void* src) {
    asm volatile("cp.async.cg.shared.global [%0], [%1], 16;" :: "r"(dst), "l"(src) : "memory");
}
#define CP_COMMIT()   asm volatile("cp.async.commit_group;" ::: "memory")
template<int N> __device__ __forceinline__ void cp_wait_group() {
    asm volatile("cp.async.wait_group %0;" :: "n"(N) : "memory");
}
#define CP_WAIT_ALL() asm volatile("cp.async.commit_group;\n\tcp.async.wait_group 0;" ::: "memory")

#define LDSM_X4(rr, addr) \
    asm volatile("ldmatrix.sync.aligned.m8n8.x4.shared.b16 {%0,%1,%2,%3}, [%4];" \
        : "=r"((rr)[0]), "=r"((rr)[1]), "=r"((rr)[2]), "=r"((rr)[3]) : "r"(addr))

#define LDSM_X4_T(rr, addr) \
    asm volatile("ldmatrix.sync.aligned.m8n8.x4.trans.shared.b16 {%0,%1,%2,%3}, [%4];" \
        : "=r"((rr)[0]), "=r"((rr)[1]), "=r"((rr)[2]), "=r"((rr)[3]) : "r"(addr))

// f16 MMA, zero-init accumulator
#define MMA_F16(d, a, b0, b1) \
    asm volatile("mma.sync.aligned.m16n8k16.row.col.f32.f16.f16.f32 " \
        "{%0,%1,%2,%3}, {%4,%5,%6,%7}, {%8,%9}, {%10,%11,%12,%13};" \
        : "=f"((d)[0]), "=f"((d)[1]), "=f"((d)[2]), "=f"((d)[3]) \
        : "r"((a)[0]), "r"((a)[1]), "r"((a)[2]), "r"((a)[3]), "r"(b0), "r"(b1), \
          "f"(0.0f), "f"(0.0f), "f"(0.0f), "f"(0.0f))

// f16 MMA, accumulate
#define MMA_F16_ACC(d, a, b0, b1) \
    asm volatile("mma.sync.aligned.m16n8k16.row.col.f32.f16.f16.f32 " \
        "{%0,%1,%2,%3}, {%4,%5,%6,%7}, {%8,%9}, {%0,%1,%2,%3};" \
        : "+f"((d)[0]), "+f"((d)[1]), "+f"((d)[2]), "+f"((d)[3]) \
        : "r"((a)[0]), "r"((a)[1]), "r"((a)[2]), "r"((a)[3]), "r"(b0), "r"(b1))

// bf16 MMA, accumulate (attention O += P @ V)
#define MMA_BF16_ACC(d, a, b0, b1) \
    asm volatile("mma.sync.aligned.m16n8k16.row.col.f32.bf16.bf16.f32 " \
        "{%0,%1,%2,%3}, {%4,%5,%6,%7}, {%8,%9}, {%0,%1,%2,%3};" \
        : "+f"((d)[0]), "+f"((d)[1]), "+f"((d)[2]), "+f"((d)[3]) \
        : "r"((a)[0]), "r"((a)[1]), "r"((a)[2]), "r"((a)[3]), "r"(b0), "r"(b1))

__device__ __forceinline__ uint32_t cvt_bf16x2(float hi, float lo) {
    uint32_t r;
    asm("cvt.rn.bf16x2.f32 %0, %1, %2;" : "=r"(r) : "f"(hi), "f"(lo));
    return r;
}
__device__ __forceinline__ uint32_t cvt_f16x2(float hi, float lo) {
    uint32_t r;
    asm("cvt.rn.f16x2.f32 %0, %1, %2;" : "=r"(r) : "f"(hi), "f"(lo));
    return r;
}
__device__ __forceinline__ float ex2f(float x) {
    float r;
    asm("ex2.approx.ftz.f32 %0, %1;" : "=f"(r) : "f"(x));
    return r;
}
__device__ __forceinline__ void prefetch_l2(const void* p) {
    asm volatile("prefetch.global.L2 [%0];" :: "l"(p));
}

// ---------------------------------------------------------------------------
// Kernel A: fused 1x1 convs + 2x2 maxpool, f16 HMMA, split-K pipelined
// (unchanged from R11 WIN).
// ---------------------------------------------------------------------------
#define CV_WOFF  0u
#define CV_XS    24576u
#define CV_XB    155648u
#define CV_SMEM  221184
#define AB_STRIDE 528

__global__ __launch_bounds__(512) void convpool_kernel(
    const float* __restrict__ x,
    const float* __restrict__ wth,
    const float* __restrict__ wph,
    const float* __restrict__ wg)
{
    extern __shared__ char smc[];
    const uint32_t sb = smem_u32(smc);
    const int ph2 = blockIdx.x, b = blockIdx.y;
    const int tid = threadIdx.x, wid = tid >> 5, lid = tid & 31;

    const char* xsrc = (const char*)(x + (size_t)b * (CC * HWV) + ph2 * 256);
    #pragma unroll
    for (int k = 0; k < 4; k++) {
        #pragma unroll
        for (int idx = tid; idx < 2048; idx += 512) {
            int c = k * 32 + (idx >> 6), ch = idx & 63;
            cp_async16(sb + CV_XS + (uint32_t)(c * 1024 + ch * 16),
                       xsrc + (size_t)c * (HWV * 4) + ch * 16);
        }
        CP_COMMIT();
    }
    for (int idx = tid; idx < 96 * 32; idx += 512) {
        int oc = idx >> 5, c4 = idx & 31;
        const float4* wsrc;
        if (oc < 16)      wsrc = (const float4*)(wth + oc * 128) + c4;
        else if (oc < 32) wsrc = (const float4*)(wph + (oc - 16) * 128) + c4;
        else              wsrc = (const float4*)(wg  + (oc - 32) * 128) + c4;
        float4 v = *wsrc;
        uint2 pk;
        pk.x = cvt_f16x2(v.y, v.x);
        pk.y = cvt_f16x2(v.w, v.z);
        int c = c4 * 4, h = c >> 6, cin = c & 63;
        *(uint2*)(smc + CV_WOFF + h * 12288 + SWZ((uint32_t)(oc * 128 + cin * 2))) = pk;
    }

    const int t = lid >> 3, r = lid & 7;
    const int rowsel = (t & 1) * 8 + r;
    const int khalf16 = (t >> 1) * 16;
    const int pg = wid * 16;
    const int xq = pg >> 6;
    const int pin = pg & 63;

    float acc[6][2][4];
    #pragma unroll
    for (int mt = 0; mt < 6; mt++)
        #pragma unroll
        for (int nt = 0; nt < 2; nt++)
            #pragma unroll
            for (int e = 0; e < 4; e++) acc[mt][nt][e] = 0.0f;

    #pragma unroll
    for (int half = 0; half < 2; half++) {
        if (half == 0) cp_wait_group<2>();
        else           cp_wait_group<0>();
        #pragma unroll
        for (int idx = tid; idx < 4096; idx += 512) {
            int c = half * 64 + (idx >> 6), p4 = idx & 63;
            float4 v = *(const float4*)(smc + CV_XS + c * 1024 + p4 * 16);
            uint2 pk;
            pk.x = cvt_f16x2(v.y, v.x);
            pk.y = cvt_f16x2(v.w, v.z);
            int p = p4 * 4, q = p >> 6, pin2 = p & 63;
            *(uint2*)(smc + CV_XB + q * 16384 + SWZ((uint32_t)(c * 128 + pin2 * 2))) = pk;
        }
        __syncthreads();
        #pragma unroll
        for (int cq = 0; cq < 4; cq++) {
            const int ks = half * 4 + cq;
            uint32_t bfr[4];
            LDSM_X4_T(bfr, sb + CV_XB + xq * 16384 +
                      SWZ((uint32_t)((ks * 16 + (t & 1) * 8 + r) * 128 + pin * 2 + (t >> 1) * 16)));
            #pragma unroll
            for (int mt = 0; mt < 6; mt++) {
                uint32_t a[4];
                LDSM_X4(a, sb + CV_WOFF + half * 12288 +
                        SWZ((uint32_t)((mt * 16 + rowsel) * 128 + cq * 32 + khalf16)));
                MMA_F16_ACC(acc[mt][0], a, bfr[0], bfr[1]);
                MMA_F16_ACC(acc[mt][1], a, bfr[2], bfr[3]);
            }
        }
        if (half == 0) __syncthreads();
    }
    __syncthreads();

    const int g = lid >> 2, tc = lid & 3;
    #pragma unroll
    for (int mt = 0; mt < 6; mt++)
        #pragma unroll
        for (int nt = 0; nt < 2; nt++) {
            uint32_t lo = cvt_f16x2(acc[mt][nt][1], acc[mt][nt][0]);
            uint32_t hi = cvt_f16x2(acc[mt][nt][3], acc[mt][nt][2]);
            uint32_t colb = (uint32_t)(pg + nt * 8 + tc * 2) * 2;
            *(uint32_t*)(smc + CV_XS + (mt * 16 + g)     * AB_STRIDE + colb) = lo;
            *(uint32_t*)(smc + CV_XS + (mt * 16 + 8 + g) * AB_STRIDE + colb) = hi;
        }
    __syncthreads();

    for (int idx = tid; idx < 1024; idx += 512) {
        int p = idx >> 2, oc0 = (idx & 3) * 4;
        float v0 = __half2float(*(const __half*)(smc + CV_XS + (oc0 + 0) * AB_STRIDE + p * 2)) * LG2E;
        float v1 = __half2float(*(const __half*)(smc + CV_XS + (oc0 + 1) * AB_STRIDE + p * 2)) * LG2E;
        float v2 = __half2float(*(const __half*)(smc + CV_XS + (oc0 + 2) * AB_STRIDE + p * 2)) * LG2E;
        float v3 = __half2float(*(const __half*)(smc + CV_XS + (oc0 + 3) * AB_STRIDE + p * 2)) * LG2E;
        uint2 pk;
        pk.x = cvt_f16x2(v1, v0);
        pk.y = cvt_f16x2(v3, v2);
        *(uint2*)(Qf + ((size_t)(b * HWV) + ph2 * 256 + p) * C8 + oc0) = pk;
    }
    for (int idx = tid; idx < 1024; idx += 512) {
        int cc = idx & 15, pw = (idx >> 4) & 31, pr = idx >> 9;
        const char* rowp = smc + CV_XS + (16 + cc) * AB_STRIDE;
        int p0 = (pr * 128 + 2 * pw) * 2;
        float v0 = __half2float(*(const __half*)(rowp + p0));
        float v1 = __half2float(*(const __half*)(rowp + p0 + 2));
        float v2 = __half2float(*(const __half*)(rowp + p0 + 128));
        float v3 = __half2float(*(const __half*)(rowp + p0 + 130));
        float m = fmaxf(fmaxf(v0, v1), fmaxf(v2, v3));
        int pj = (2 * ph2 + pr) * 32 + pw;
        Kf[((size_t)(b * PJV) + pj) * C8 + cc] = __float2half(m);
    }
    for (int idx = tid; idx < 4096; idx += 512) {
        int cc = idx & 63, pw = (idx >> 6) & 31, pr = idx >> 11;
        const char* rowp = smc + CV_XS + (32 + cc) * AB_STRIDE;
        int p0 = (pr * 128 + 2 * pw) * 2;
        float v0 = __half2float(*(const __half*)(rowp + p0));
        float v1 = __half2float(*(const __half*)(rowp + p0 + 2));
        float v2 = __half2float(*(const __half*)(rowp + p0 + 128));
        float v3 = __half2float(*(const __half*)(rowp + p0 + 130));
        float m = fmaxf(fmaxf(v0, v1), fmaxf(v2, v3));
        int pj = (2 * ph2 + pr) * 32 + pw;
        Vg[((size_t)(b * PJV) + pj) * C2 + cc] = __float2bfloat16(m);
    }
}

// ---------------------------------------------------------------------------
// Kernel B: FUSED flash attention + output conv + residual.
// 1 CTA per (b, 256-query tile), 256 threads, 184KB smem, single wave.
// After flash loop: o staged f16 into dead K region, w_o HMMA in-CTA,
// gamma*acc staged into dead V region, out = x + staged (coalesced 1KB rows).
// x tile L2-prefetched during the flash loop.
// ---------------------------------------------------------------------------
#define QOFF   0u          // Q f16 [256][32B]              = 8192
#define KOFF   8192u       // K f16 32KB -> o-stage [256 pos][128B]
#define VOFF   40960u      // V bf16 128KB -> gamma*acc stage [128 oc][520B]
#define WOOFF  172032u     // wo f16 [128 oc][128B]         = 16384
#define AT_SMEM 188416

__global__ __launch_bounds__(256, 1) void attn_kernel(
    const float* __restrict__ x,
    const float* __restrict__ wo,
    const float* __restrict__ gptr,
    float* __restrict__ out)
{
    extern __shared__ char smc[];
    const uint32_t sb = smem_u32(smc);
    const int tid = threadIdx.x, wid = tid >> 5, lid = tid & 31;
    const int b = blockIdx.y, m0 = blockIdx.x * 256;

    // ---- prologue: issue Q + all 8 KV groups ----
    {
        const char* qsrc = (const char*)(Qf + ((size_t)(b * HWV) + m0) * C8);
        const char* ksrc = (const char*)(Kf + (size_t)b * PJV * C8);
        const char* vsrc = (const char*)(Vg + (size_t)b * PJV * C2);
        const int jk = tid >> 1, kh = (tid & 1) * 16;
        #pragma unroll
        for (int gq = 0; gq < 8; gq++) {
            if (gq == 0) {
                cp_async16(sb + QOFF + SWZ(tid * 32),      qsrc + tid * 32);
                cp_async16(sb + QOFF + SWZ(tid * 32 + 16), qsrc + tid * 32 + 16);
            }
            int j = gq * 128 + jk;
            cp_async16(sb + KOFF + SWZ(j * 32 + kh), ksrc + j * 32 + kh);
            #pragma unroll
            for (int v = 0; v < 4; v++) {
                int idx = gq * 1024 + v * 256 + tid;
                cp_async16(sb + VOFF + SWZ(idx * 16), vsrc + idx * 16);
            }
            CP_COMMIT();
        }
    }
    // ---- stage wo fp32 -> f16 while loads fly ----
    for (int idx = tid; idx < 2048; idx += 256) {
        int oc = idx >> 4, c4 = idx & 15;
        float4 v = *((const float4*)(wo + oc * 64) + c4);
        uint2 pk;
        pk.x = cvt_f16x2(v.y, v.x);
        pk.y = cvt_f16x2(v.w, v.z);
        *(uint2*)(smc + WOOFF + SWZ((uint32_t)(oc * 128 + c4 * 8))) = pk;
    }

    const int t  = lid >> 3, r = lid & 7;
    const int rowsel = (t & 1) * 8 + r;
    const int khalf  = (t >> 1) * 16;

    cp_wait_group<7>();
    __syncthreads();

    uint32_t qa[4], qb[4];
    LDSM_X4(qa, sb + QOFF + SWZ((uint32_t)((wid * 32 + rowsel) * 32 + khalf)));
    LDSM_X4(qb, sb + QOFF + SWZ((uint32_t)((wid * 32 + 16 + rowsel) * 32 + khalf)));

    float oacc[2][8][4];
    #pragma unroll
    for (int mt = 0; mt < 2; mt++)
        #pragma unroll
        for (int nt = 0; nt < 8; nt++)
            #pragma unroll
            for (int e = 0; e < 4; e++) oacc[mt][nt][e] = 0.0f;
    float lsum[2][2] = {{0.0f, 0.0f}, {0.0f, 0.0f}};

    const uint32_t kladdr_base = (uint32_t)(rowsel * 32 + khalf);
    const uint32_t vladdr_row  = (uint32_t)((t & 1) * 8 + r) * 128 + (uint32_t)((t >> 1) * 8) * 2;
    const float* xtile = x + (size_t)b * (CC * HWV) + m0;

    #pragma unroll
    for (int gq = 0; gq < 8; gq++) {
        if (gq > 0) {
            if (gq == 1)      cp_wait_group<6>();
            else if (gq == 2) cp_wait_group<5>();
            else if (gq == 3) cp_wait_group<4>();
            else if (gq == 4) cp_wait_group<3>();
            else if (gq == 5) cp_wait_group<2>();
            else if (gq == 6) cp_wait_group<1>();
            else              cp_wait_group<0>();
            __syncthreads();
        }
        // L2-prefetch x tile: 128 sectors/group (1024 total = 128 rows x 8)
        if (tid < 128) {
            int sector = gq * 128 + tid;
            prefetch_l2((const char*)(xtile + (size_t)(sector >> 3) * HWV) + (sector & 7) * 128);
        }
        #pragma unroll 2
        for (int jt8 = 0; jt8 < 8; jt8++) {
            const uint32_t j0 = (uint32_t)(gq * 8 + jt8) * 16;
            uint32_t kb[4];
            LDSM_X4(kb, sb + KOFF + SWZ(kladdr_base + j0 * 32));

            float sA0[4], sA1[4], sB0[4], sB1[4];
            MMA_F16(sA0, qa, kb[0], kb[2]);
            MMA_F16(sA1, qa, kb[1], kb[3]);
            MMA_F16(sB0, qb, kb[0], kb[2]);
            MMA_F16(sB1, qb, kb[1], kb[3]);

            uint32_t pA[4], pB[4];
            {
                float e0 = ex2f(sA0[0]), e1 = ex2f(sA0[1]), e2 = ex2f(sA0[2]), e3 = ex2f(sA0[3]);
                float f0 = ex2f(sA1[0]), f1 = ex2f(sA1[1]), f2 = ex2f(sA1[2]), f3 = ex2f(sA1[3]);
                lsum[0][0] += e0 + e1 + f0 + f1;
                lsum[0][1] += e2 + e3 + f2 + f3;
                pA[0] = cvt_bf16x2(e1, e0); pA[1] = cvt_bf16x2(e3, e2);
                pA[2] = cvt_bf16x2(f1, f0); pA[3] = cvt_bf16x2(f3, f2);
            }
            {
                float e0 = ex2f(sB0[0]), e1 = ex2f(sB0[1]), e2 = ex2f(sB0[2]), e3 = ex2f(sB0[3]);
                float f0 = ex2f(sB1[0]), f1 = ex2f(sB1[1]), f2 = ex2f(sB1[2]), f3 = ex2f(sB1[3]);
                lsum[1][0] += e0 + e1 + f0 + f1;
                lsum[1][1] += e2 + e3 + f2 + f3;
                pB[0] = cvt_bf16x2(e1, e0); pB[1] = cvt_bf16x2(e3, e2);
                pB[2] = cvt_bf16x2(f1, f0); pB[3] = cvt_bf16x2(f3, f2);
            }

            #pragma unroll
            for (int cq = 0; cq < 4; cq++) {
                uint32_t vb[4];
                LDSM_X4_T(vb, sb + VOFF + SWZ(vladdr_row + j0 * 128 + (uint32_t)cq * 32));
                MMA_BF16_ACC(oacc[0][2 * cq],     pA, vb[0], vb[1]);
                MMA_BF16_ACC(oacc[0][2 * cq + 1], pA, vb[2], vb[3]);
                MMA_BF16_ACC(oacc[1][2 * cq],     pB, vb[0], vb[1]);
                MMA_BF16_ACC(oacc[1][2 * cq + 1], pB, vb[2], vb[3]);
            }
        }
    }

    #pragma unroll
    for (int mt = 0; mt < 2; mt++)
        #pragma unroll
        for (int hh = 0; hh < 2; hh++) {
            float l = lsum[mt][hh];
            l += __shfl_xor_sync(0xffffffffu, l, 1);
            l += __shfl_xor_sync(0xffffffffu, l, 2);
            lsum[mt][hh] = 1.0f / l;
        }

    // ---- stage normalized o (f16) into dead K region [256 pos][128B] ----
    __syncthreads();   // all warps done reading K/V
    const int g = lid >> 2, tc = lid & 3;
    #pragma unroll
    for (int mt = 0; mt < 2; mt++) {
        int mlocal = wid * 32 + mt * 16 + g;
        #pragma unroll
        for (int nt = 0; nt < 8; nt++) {
            uint32_t colb = (uint32_t)(nt * 8 + tc * 2) * 2;
            uint32_t w0 = cvt_f16x2(oacc[mt][nt][1] * lsum[mt][0],
                                    oacc[mt][nt][0] * lsum[mt][0]);
            uint32_t w1 = cvt_f16x2(oacc[mt][nt][3] * lsum[mt][1],
                                    oacc[mt][nt][2] * lsum[mt][1]);
            *(uint32_t*)(smc + KOFF + SWZ((uint32_t)(mlocal * 128) + colb))       = w0;
            *(uint32_t*)(smc + KOFF + SWZ((uint32_t)((mlocal + 8) * 128) + colb)) = w1;
        }
    }
    __syncthreads();

    // ---- epilogue MMA: warp -> oc0 = (wid>>2)*64, pos0 = (wid&3)*64 ----
    const int oc0 = (wid >> 2) * 64, pos0 = (wid & 3) * 64;
    float acc2[4][8][4];
    #pragma unroll
    for (int mt2 = 0; mt2 < 4; mt2++)
        #pragma unroll
        for (int nt = 0; nt < 8; nt++)
            #pragma unroll
            for (int e = 0; e < 4; e++) acc2[mt2][nt][e] = 0.0f;

    #pragma unroll
    for (int ks = 0; ks < 4; ks++) {
        uint32_t a[4][4];
        #pragma unroll
        for (int mt2 = 0; mt2 < 4; mt2++)
            LDSM_X4(a[mt2], sb + WOOFF +
                    SWZ((uint32_t)((oc0 + mt2 * 16 + rowsel) * 128 + ks * 32 + khalf)));
        #pragma unroll
        for (int nt2 = 0; nt2 < 4; nt2++) {
            uint32_t bfr[4];
            LDSM_X4(bfr, sb + KOFF +
                    SWZ((uint32_t)((pos0 + nt2 * 16 + rowsel) * 128 + ks * 32 + khalf)));
            #pragma unroll
            for (int mt2 = 0; mt2 < 4; mt2++) {
                MMA_F16_ACC(acc2[mt2][2 * nt2],     a[mt2], bfr[0], bfr[2]);
                MMA_F16_ACC(acc2[mt2][2 * nt2 + 1], a[mt2], bfr[1], bfr[3]);
            }
        }
    }

    // ---- stage gamma*acc into dead V region [128 oc][520B stride] ----
    const float gamma = __ldg(gptr);
    #pragma unroll
    for (int mt2 = 0; mt2 < 4; mt2++) {
        int row0 = oc0 + mt2 * 16 + g;
        #pragma unroll
        for (int nt = 0; nt < 8; nt++) {
            int colb = (pos0 + nt * 8 + tc * 2) * 2;
            uint32_t lo = cvt_f16x2(gamma * acc2[mt2][nt][1], gamma * acc2[mt2][nt][0]);
            uint32_t hi = cvt_f16x2(gamma * acc2[mt2][nt][3], gamma * acc2[mt2][nt][2]);
            *(uint32_t*)(smc + VOFF + row0 * 520 + colb)       = lo;
            *(uint32_t*)(smc + VOFF + (row0 + 8) * 520 + colb) = hi;
        }
    }
    __syncthreads();

    // ---- streaming: out = x + staged, 1KB-coalesced rows (x is L2-hot) ----
    #pragma unroll 4
    for (int i = tid; i < 8192; i += 256) {
        int oc = i >> 6, ch = i & 63;
        uint2 pk = *(const uint2*)(smc + VOFF + oc * 520 + ch * 8);
        float2 f0 = __half22float2(*(__half2*)&pk.x);
        float2 f1 = __half22float2(*(__half2*)&pk.y);
        size_t off = ((size_t)(b * CC) + oc) * HWV + m0 + ch * 4;
        float4 xv = *(const float4*)(x + off);
        float4 w;
        w.x = xv.x + f0.x; w.y = xv.y + f0.y;
        w.z = xv.z + f1.x; w.w = xv.w + f1.y;
        *(float4*)(out + off) = w;
    }
}

// ---------------------------------------------------------------------------
extern "C" void kernel_launch(void* const* d_in, const int* in_sizes, int n_in,
                              void* d_out, int out_size)
{
    const float* x   = (const float*)d_in[0];
    const float* wth = (const float*)d_in[1];
    const float* wph = (const float*)d_in[2];
    const float* wg  = (const float*)d_in[3];
    const float* wo  = (const float*)d_in[4];
    const float* gmm = (const float*)d_in[5];
    float* out = (float*)d_out;

    cudaFuncSetAttribute(convpool_kernel, cudaFuncAttributeMaxDynamicSharedMemorySize, CV_SMEM);
    cudaFuncSetAttribute(attn_kernel,     cudaFuncAttributeMaxDynamicSharedMemorySize, AT_SMEM);

    convpool_kernel<<<dim3(16, 8), 512, CV_SMEM>>>(x, wth, wph, wg);
    attn_kernel<<<dim3(16, 8), 256, AT_SMEM>>>(x, wo, gmm, out);
}

// round 14
// speedup vs baseline: 1.0437x; 1.0437x over previous
#include <cuda_runtime.h>
#include <cuda_bf16.h>
#include <cuda_fp16.h>
#include <cstdint>

// Problem constants
#define BB    8
#define CC    128
#define HWV   4096       // H*W
#define PJV   1024       // pooled positions
#define C8    16
#define C2    64
#define LG2E  1.44269504f

// Scratch (device globals; no allocation allowed)
__device__ __align__(16) __half         Qf [BB * HWV * C8];   // 1 MB   (pre-scaled by log2e)
__device__ __align__(16) __half         Kf [BB * PJV * C8];   // 256 KB
__device__ __align__(16) __nv_bfloat16  Vg [BB * PJV * C2];   // 1 MB   (bf16: pairs with bf16 P)
__device__ __align__(16) __half         Og [BB * HWV * C2];   // 4 MB   (normalized attn out)

// ===================== helpers =============================================
__device__ __forceinline__ uint32_t smem_u32(const void* p) {
    uint32_t a;
    asm("{ .reg .u64 t; cvta.to.shared.u64 t, %1; cvt.u32.u64 %0, t; }" : "=r"(a) : "l"(p));
    return a;
}
#define SWZ(o) ((o) ^ (((o) >> 3) & 0x70))

__device__ __forceinline__ void cp_async16(uint32_t dst, const void* src) {
    asm volatile("cp.async.cg.shared.global [%0], [%1], 16;" :: "r"(dst), "l"(src) : "memory");
}
#define CP_COMMIT()   asm volatile("cp.async.commit_group;" ::: "memory")
template<int N> __device__ __forceinline__ void cp_wait_group() {
    asm volatile("cp.async.wait_group %0;" :: "n"(N) : "memory");
}
#define CP_WAIT_ALL() asm volatile("cp.async.commit_group;\n\tcp.async.wait_group 0;" ::: "memory")

// bulk DMA: one instruction per (large) copy — kills LDGSTS issue pressure
__device__ __forceinline__ void bulk_g2s(uint32_t dst, const void* src,
                                         uint32_t bytes, uint32_t mbar) {
    asm volatile(
        "cp.async.bulk.shared::cluster.global.mbarrier::complete_tx::bytes "
        "[%0], [%1], %2, [%3];"
        :: "r"(dst), "l"(src), "r"(bytes), "r"(mbar) : "memory");
}
#define MBAR_INIT(a, c) asm volatile("mbarrier.init.shared.b64 [%0], %1;" :: "r"((uint32_t)(a)), "r"((uint32_t)(c)) : "memory")
#define MBAR_EXPECT_TX(a, n) asm volatile("mbarrier.arrive.expect_tx.shared.b64 _, [%0], %1;" :: "r"((uint32_t)(a)), "r"((uint32_t)(n)) : "memory")
#define MBAR_WAIT(a, ph) do { \
    uint32_t _m = (uint32_t)(a), _p = (uint32_t)(ph), _d; \
    asm volatile("{ .reg .pred p; mbarrier.try_wait.parity.acquire.cta.shared::cta.b64 p, [%1], %2; selp.b32 %0,1,0,p; }" \
        : "=r"(_d) : "r"(_m), "r"(_p) : "memory"); \
    if (!_d) { \
        asm volatile("{ .reg .pred P1; WL_%=: mbarrier.try_wait.parity.acquire.cta.shared::cta.b64 P1, [%0], %1, 0x989680; @P1 bra.uni WD_%=; bra.uni WL_%=; WD_%=: }" \
            :: "r"(_m), "r"(_p) : "memory"); \
    } } while (0)

#define LDSM_X4(rr, addr) \
    asm volatile("ldmatrix.sync.aligned.m8n8.x4.shared.b16 {%0,%1,%2,%3}, [%4];" \
        : "=r"((rr)[0]), "=r"((rr)[1]), "=r"((rr)[2]), "=r"((rr)[3]) : "r"(addr))

#define LDSM_X4_T(rr, addr) \
    asm volatile("ldmatrix.sync.aligned.m8n8.x4.trans.shared.b16 {%0,%1,%2,%3}, [%4];" \
        : "=r"((rr)[0]), "=r"((rr)[1]), "=r"((rr)[2]), "=r"((rr)[3]) : "r"(addr))

// f16 MMA, zero-init accumulator
#define MMA_F16(d, a, b0, b1) \
    asm volatile("mma.sync.aligned.m16n8k16.row.col.f32.f16.f16.f32 " \
        "{%0,%1,%2,%3}, {%4,%5,%6,%7}, {%8,%9}, {%10,%11,%12,%13};" \
        : "=f"((d)[0]), "=f"((d)[1]), "=f"((d)[2]), "=f"((d)[3]) \
        : "r"((a)[0]), "r"((a)[1]), "r"((a)[2]), "r"((a)[3]), "r"(b0), "r"(b1), \
          "f"(0.0f), "f"(0.0f), "f"(0.0f), "f"(0.0f))

// f16 MMA, accumulate
#define MMA_F16_ACC(d, a, b0, b1) \
    asm volatile("mma.sync.aligned.m16n8k16.row.col.f32.f16.f16.f32 " \
        "{%0,%1,%2,%3}, {%4,%5,%6,%7}, {%8,%9}, {%0,%1,%2,%3};" \
        : "+f"((d)[0]), "+f"((d)[1]), "+f"((d)[2]), "+f"((d)[3]) \
        : "r"((a)[0]), "r"((a)[1]), "r"((a)[2]), "r"((a)[3]), "r"(b0), "r"(b1))

// bf16 MMA, accumulate (attention O += P @ V)
#define MMA_BF16_ACC(d, a, b0, b1) \
    asm volatile("mma.sync.aligned.m16n8k16.row.col.f32.bf16.bf16.f32 " \
        "{%0,%1,%2,%3}, {%4,%5,%6,%7}, {%8,%9}, {%0,%1,%2,%3};" \
        : "+f"((d)[0]), "+f"((d)[1]), "+f"((d)[2]), "+f"((d)[3]) \
        : "r"((a)[0]), "r"((a)[1]), "r"((a)[2]), "r"((a)[3]), "r"(b0), "r"(b1))

__device__ __forceinline__ uint32_t cvt_bf16x2(float hi, float lo) {
    uint32_t r;
    asm("cvt.rn.bf16x2.f32 %0, %1, %2;" : "=r"(r) : "f"(hi), "f"(lo));
    return r;
}
__device__ __forceinline__ uint32_t cvt_f16x2(float hi, float lo) {
    uint32_t r;
    asm("cvt.rn.f16x2.f32 %0, %1, %2;" : "=r"(r) : "f"(hi), "f"(lo));
    return r;
}
__device__ __forceinline__ float ex2f(float x) {
    float r;
    asm("ex2.approx.ftz.f32 %0, %1;" : "=f"(r) : "f"(x));
    return r;
}

// ---------------------------------------------------------------------------
// Kernel A: fused 1x1 convs + 2x2 maxpool, f16 HMMA, split-K pipelined.
// x loaded via cp.async.bulk (128 row-DMAs of 1KB, 2 mbarrier chunks) —
// replaces 8192 LDGSTS with 128 UBLKCP, removing the LSU issue bottleneck.
// ---------------------------------------------------------------------------
#define CV_WOFF  0u          // W f16 [h:2][oc:96][128B]        = 24576
#define CV_XS    24576u      // fp32 staging [c:128][1024B]     = 131072 (accbuf overlays)
#define CV_XB    155648u     // f16 x [q:4][c:128][128B]        = 65536
#define CV_MB    221184u     // 2 mbarriers
#define CV_SMEM  221216
#define AB_STRIDE 528        // accbuf f16 row stride (bytes)

__global__ __launch_bounds__(512) void convpool_kernel(
    const float* __restrict__ x,
    const float* __restrict__ wth,
    const float* __restrict__ wph,
    const float* __restrict__ wg)
{
    extern __shared__ char smc[];
    const uint32_t sb = smem_u32(smc);
    const int ph2 = blockIdx.x, b = blockIdx.y;
    const int tid = threadIdx.x, wid = tid >> 5, lid = tid & 31;

    // ---- mbarrier setup + bulk row-DMAs (c-row = 1KB contiguous) ----
    if (tid == 0) {
        MBAR_INIT(sb + CV_MB, 1);
        MBAR_INIT(sb + CV_MB + 8, 1);
    }
    __syncthreads();
    const char* xsrc = (const char*)(x + (size_t)b * (CC * HWV) + ph2 * 256);
    if (tid == 0) {
        MBAR_EXPECT_TX(sb + CV_MB,     65536);
        MBAR_EXPECT_TX(sb + CV_MB + 8, 65536);
    }
    __syncthreads();
    if (tid < 128) {
        int c = tid;
        uint32_t mb = sb + CV_MB + ((uint32_t)(c >> 6) << 3);
        bulk_g2s(sb + CV_XS + (uint32_t)c * 1024,
                 xsrc + (size_t)c * (HWV * 4), 1024, mb);
    }
    // ---- stage W (96x128 fp32 -> f16, swizzled c-halves); overlaps DMA ----
    for (int idx = tid; idx < 96 * 32; idx += 512) {
        int oc = idx >> 5, c4 = idx & 31;
        const float4* wsrc;
        if (oc < 16)      wsrc = (const float4*)(wth + oc * 128) + c4;
        else if (oc < 32) wsrc = (const float4*)(wph + (oc - 16) * 128) + c4;
        else              wsrc = (const float4*)(wg  + (oc - 32) * 128) + c4;
        float4 v = *wsrc;
        uint2 pk;
        pk.x = cvt_f16x2(v.y, v.x);
        pk.y = cvt_f16x2(v.w, v.z);
        int c = c4 * 4, h = c >> 6, cin = c & 63;
        *(uint2*)(smc + CV_WOFF + h * 12288 + SWZ((uint32_t)(oc * 128 + cin * 2))) = pk;
    }

    // MMA lane constants
    const int t = lid >> 3, r = lid & 7;
    const int rowsel = (t & 1) * 8 + r;
    const int khalf16 = (t >> 1) * 16;
    const int pg = wid * 16;
    const int xq = pg >> 6;
    const int pin = pg & 63;

    float acc[6][2][4];
    #pragma unroll
    for (int mt = 0; mt < 6; mt++)
        #pragma unroll
        for (int nt = 0; nt < 2; nt++)
            #pragma unroll
            for (int e = 0; e < 4; e++) acc[mt][nt][e] = 0.0f;

    #pragma unroll
    for (int half = 0; half < 2; half++) {
        MBAR_WAIT(sb + CV_MB + (uint32_t)(half << 3), 0);
        // convert 64 c-rows fp32 -> f16 swizzled, uint4 stores (8 pos/thread)
        #pragma unroll
        for (int idx = tid; idx < 2048; idx += 512) {
            int c = half * 64 + (idx >> 5), p8 = (idx & 31) * 8;
            const float4* s = (const float4*)(smc + CV_XS + c * 1024 + p8 * 4);
            float4 v0 = s[0], v1 = s[1];
            uint4 pk;
            pk.x = cvt_f16x2(v0.y, v0.x);
            pk.y = cvt_f16x2(v0.w, v0.z);
            pk.z = cvt_f16x2(v1.y, v1.x);
            pk.w = cvt_f16x2(v1.w, v1.z);
            int q = p8 >> 6, pin2 = p8 & 63;
            *(uint4*)(smc + CV_XB + q * 16384 + SWZ((uint32_t)(c * 128 + pin2 * 2))) = pk;
        }
        __syncthreads();
        #pragma unroll
        for (int cq = 0; cq < 4; cq++) {
            const int ks = half * 4 + cq;
            uint32_t bfr[4];
            LDSM_X4_T(bfr, sb + CV_XB + xq * 16384 +
                      SWZ((uint32_t)((ks * 16 + (t & 1) * 8 + r) * 128 + pin * 2 + (t >> 1) * 16)));
            #pragma unroll
            for (int mt = 0; mt < 6; mt++) {
                uint32_t a[4];
                LDSM_X4(a, sb + CV_WOFF + half * 12288 +
                        SWZ((uint32_t)((mt * 16 + rowsel) * 128 + cq * 32 + khalf16)));
                MMA_F16_ACC(acc[mt][0], a, bfr[0], bfr[1]);
                MMA_F16_ACC(acc[mt][1], a, bfr[2], bfr[3]);
            }
        }
        if (half == 0) __syncthreads();
    }
    __syncthreads();   // staging region dead -> accbuf overlay

    // ---- accum -> smem f16 accbuf [96 oc][528B stride] ----
    const int g = lid >> 2, tc = lid & 3;
    #pragma unroll
    for (int mt = 0; mt < 6; mt++)
        #pragma unroll
        for (int nt = 0; nt < 2; nt++) {
            uint32_t lo = cvt_f16x2(acc[mt][nt][1], acc[mt][nt][0]);
            uint32_t hi = cvt_f16x2(acc[mt][nt][3], acc[mt][nt][2]);
            uint32_t colb = (uint32_t)(pg + nt * 8 + tc * 2) * 2;
            *(uint32_t*)(smc + CV_XS + (mt * 16 + g)     * AB_STRIDE + colb) = lo;
            *(uint32_t*)(smc + CV_XS + (mt * 16 + 8 + g) * AB_STRIDE + colb) = hi;
        }
    __syncthreads();

    // ---- theta (oc 0..15) -> Qf, pre-scaled by log2e, uint2 coalesced ----
    for (int idx = tid; idx < 1024; idx += 512) {
        int p = idx >> 2, oc0 = (idx & 3) * 4;
        float v0 = __half2float(*(const __half*)(smc + CV_XS + (oc0 + 0) * AB_STRIDE + p * 2)) * LG2E;
        float v1 = __half2float(*(const __half*)(smc + CV_XS + (oc0 + 1) * AB_STRIDE + p * 2)) * LG2E;
        float v2 = __half2float(*(const __half*)(smc + CV_XS + (oc0 + 2) * AB_STRIDE + p * 2)) * LG2E;
        float v3 = __half2float(*(const __half*)(smc + CV_XS + (oc0 + 3) * AB_STRIDE + p * 2)) * LG2E;
        uint2 pk;
        pk.x = cvt_f16x2(v1, v0);
        pk.y = cvt_f16x2(v3, v2);
        *(uint2*)(Qf + ((size_t)(b * HWV) + ph2 * 256 + p) * C8 + oc0) = pk;
    }
    // ---- pool K (phi rows 16..31): lanes vary channel -> coalesced 2B ----
    for (int idx = tid; idx < 1024; idx += 512) {
        int cc = idx & 15, pw = (idx >> 4) & 31, pr = idx >> 9;
        const char* rowp = smc + CV_XS + (16 + cc) * AB_STRIDE;
        int p0 = (pr * 128 + 2 * pw) * 2;
        float v0 = __half2float(*(const __half*)(rowp + p0));
        float v1 = __half2float(*(const __half*)(rowp + p0 + 2));
        float v2 = __half2float(*(const __half*)(rowp + p0 + 128));
        float v3 = __half2float(*(const __half*)(rowp + p0 + 130));
        float m = fmaxf(fmaxf(v0, v1), fmaxf(v2, v3));
        int pj = (2 * ph2 + pr) * 32 + pw;
        Kf[((size_t)(b * PJV) + pj) * C8 + cc] = __float2half(m);
    }
    // ---- pool V (g rows 32..95): lanes vary channel -> coalesced 2B ----
    for (int idx = tid; idx < 4096; idx += 512) {
        int cc = idx & 63, pw = (idx >> 6) & 31, pr = idx >> 11;
        const char* rowp = smc + CV_XS + (32 + cc) * AB_STRIDE;
        int p0 = (pr * 128 + 2 * pw) * 2;
        float v0 = __half2float(*(const __half*)(rowp + p0));
        float v1 = __half2float(*(const __half*)(rowp + p0 + 2));
        float v2 = __half2float(*(const __half*)(rowp + p0 + 128));
        float v3 = __half2float(*(const __half*)(rowp + p0 + 130));
        float m = fmaxf(fmaxf(v0, v1), fmaxf(v2, v3));
        int pj = (2 * ph2 + pr) * 32 + pw;
        Vg[((size_t)(b * PJV) + pj) * C2 + cc] = __float2bfloat16(m);
    }
}

// ---------------------------------------------------------------------------
// Kernel B: HMMA flash attention (exact R11 WIN version).
// ---------------------------------------------------------------------------
#define QOFF  0u
#define KOFF  8192u
#define VOFF  40960u

__global__ __launch_bounds__(256, 1) void attn_kernel()
{
    extern __shared__ char smc[];
    const uint32_t sb = smem_u32(smc);
    const int tid = threadIdx.x, wid = tid >> 5, lid = tid & 31;
    const int b = blockIdx.y, m0 = blockIdx.x * 256;

    {
        const char* qsrc = (const char*)(Qf + ((size_t)(b * HWV) + m0) * C8);
        int m = tid;
        cp_async16(sb + QOFF + SWZ(m * 32),      qsrc + m * 32);
        cp_async16(sb + QOFF + SWZ(m * 32 + 16), qsrc + m * 32 + 16);

        const char* ksrc = (const char*)(Kf + (size_t)b * PJV * C8);
        #pragma unroll
        for (int j = tid; j < PJV; j += 256) {
            cp_async16(sb + KOFF + SWZ(j * 32),      ksrc + j * 32);
            cp_async16(sb + KOFF + SWZ(j * 32 + 16), ksrc + j * 32 + 16);
        }
        const char* vsrc = (const char*)(Vg + (size_t)b * PJV * C2);
        #pragma unroll
        for (int idx = tid; idx < PJV * 8; idx += 256)
            cp_async16(sb + VOFF + SWZ(idx * 16), vsrc + idx * 16);
        CP_WAIT_ALL();
    }
    __syncthreads();

    const int t  = lid >> 3, r = lid & 7;
    const int rowsel = (t & 1) * 8 + r;
    const int khalf  = (t >> 1) * 16;

    uint32_t qa[4], qb[4];
    LDSM_X4(qa, sb + QOFF + SWZ((uint32_t)((wid * 32 + rowsel) * 32 + khalf)));
    LDSM_X4(qb, sb + QOFF + SWZ((uint32_t)((wid * 32 + 16 + rowsel) * 32 + khalf)));

    float oacc[2][8][4];
    #pragma unroll
    for (int mt = 0; mt < 2; mt++)
        #pragma unroll
        for (int nt = 0; nt < 8; nt++)
            #pragma unroll
            for (int e = 0; e < 4; e++) oacc[mt][nt][e] = 0.0f;
    float lsum[2][2] = {{0.0f, 0.0f}, {0.0f, 0.0f}};

    const uint32_t kladdr_base = (uint32_t)(rowsel * 32 + khalf);
    const uint32_t vladdr_row  = (uint32_t)((t & 1) * 8 + r) * 128 + (uint32_t)((t >> 1) * 8) * 2;

    #pragma unroll 2
    for (int jt = 0; jt < 64; jt++) {
        const uint32_t j0 = (uint32_t)jt * 16;
        uint32_t kb[4];
        LDSM_X4(kb, sb + KOFF + SWZ(kladdr_base + j0 * 32));

        float sA0[4], sA1[4], sB0[4], sB1[4];
        MMA_F16(sA0, qa, kb[0], kb[2]);
        MMA_F16(sA1, qa, kb[1], kb[3]);
        MMA_F16(sB0, qb, kb[0], kb[2]);
        MMA_F16(sB1, qb, kb[1], kb[3]);

        uint32_t pA[4], pB[4];
        {
            float e0 = ex2f(sA0[0]), e1 = ex2f(sA0[1]), e2 = ex2f(sA0[2]), e3 = ex2f(sA0[3]);
            float f0 = ex2f(sA1[0]), f1 = ex2f(sA1[1]), f2 = ex2f(sA1[2]), f3 = ex2f(sA1[3]);
            lsum[0][0] += e0 + e1 + f0 + f1;
            lsum[0][1] += e2 + e3 + f2 + f3;
            pA[0] = cvt_bf16x2(e1, e0); pA[1] = cvt_bf16x2(e3, e2);
            pA[2] = cvt_bf16x2(f1, f0); pA[3] = cvt_bf16x2(f3, f2);
        }
        {
            float e0 = ex2f(sB0[0]), e1 = ex2f(sB0[1]), e2 = ex2f(sB0[2]), e3 = ex2f(sB0[3]);
            float f0 = ex2f(sB1[0]), f1 = ex2f(sB1[1]), f2 = ex2f(sB1[2]), f3 = ex2f(sB1[3]);
            lsum[1][0] += e0 + e1 + f0 + f1;
            lsum[1][1] += e2 + e3 + f2 + f3;
            pB[0] = cvt_bf16x2(e1, e0); pB[1] = cvt_bf16x2(e3, e2);
            pB[2] = cvt_bf16x2(f1, f0); pB[3] = cvt_bf16x2(f3, f2);
        }

        #pragma unroll
        for (int cq = 0; cq < 4; cq++) {
            uint32_t vb[4];
            LDSM_X4_T(vb, sb + VOFF + SWZ(vladdr_row + j0 * 128 + (uint32_t)cq * 32));
            MMA_BF16_ACC(oacc[0][2 * cq],     pA, vb[0], vb[1]);
            MMA_BF16_ACC(oacc[0][2 * cq + 1], pA, vb[2], vb[3]);
            MMA_BF16_ACC(oacc[1][2 * cq],     pB, vb[0], vb[1]);
            MMA_BF16_ACC(oacc[1][2 * cq + 1], pB, vb[2], vb[3]);
        }
    }

    #pragma unroll
    for (int mt = 0; mt < 2; mt++)
        #pragma unroll
        for (int hh = 0; hh < 2; hh++) {
            float l = lsum[mt][hh];
            l += __shfl_xor_sync(0xffffffffu, l, 1);
            l += __shfl_xor_sync(0xffffffffu, l, 2);
            lsum[mt][hh] = 1.0f / l;
        }

    const int g = lid >> 2, tc = lid & 3;
    #pragma unroll
    for (int mt = 0; mt < 2; mt++) {
        int mrow = m0 + wid * 32 + mt * 16 + g;
        __half* o0 = Og + ((size_t)(b * HWV) + mrow) * C2;
        __half* o1 = o0 + 8 * C2;
        #pragma unroll
        for (int nt = 0; nt < 8; nt++) {
            uint32_t w0 = cvt_f16x2(oacc[mt][nt][1] * lsum[mt][0],
                                    oacc[mt][nt][0] * lsum[mt][0]);
            uint32_t w1 = cvt_f16x2(oacc[mt][nt][3] * lsum[mt][1],
                                    oacc[mt][nt][2] * lsum[mt][1]);
            *(uint32_t*)(o0 + nt * 8 + tc * 2) = w0;
            *(uint32_t*)(o1 + nt * 8 + tc * 2) = w1;
        }
    }
}

// ---------------------------------------------------------------------------
// Kernel C: out = x + gamma * (w_o @ o), f16 HMMA + staged coalesced I/O
// (exact R11 WIN version).
// ---------------------------------------------------------------------------
#define EP_WOFF 0u
#define EP_OOFF 16384u
#define EP_RB   0u
#define EP_SMEM 34816

__global__ __launch_bounds__(256) void epilogue_kernel(
    const float* __restrict__ x,
    const float* __restrict__ wo,
    const float* __restrict__ gptr,
    float* __restrict__ out)
{
    extern __shared__ char smc[];
    const uint32_t sb = smem_u32(smc);
    const int it = blockIdx.x, b = blockIdx.y;
    const int i0 = it * 128;
    const int tid = threadIdx.x, wid = tid >> 5, lid = tid & 31;

    const char* osrc = (const char*)(Og + ((size_t)(b * HWV) + i0) * C2);
    #pragma unroll
    for (int idx = tid; idx < 1024; idx += 256) {
        int p = idx >> 3, ch = idx & 7;
        cp_async16(sb + EP_OOFF + SWZ((uint32_t)(p * 128 + ch * 16)), osrc + idx * 16);
    }
    for (int idx = tid; idx < 2048; idx += 256) {
        int oc = idx >> 4, c4 = idx & 15;
        float4 v = *((const float4*)(wo + oc * 64) + c4);
        uint2 pk;
        pk.x = cvt_f16x2(v.y, v.x);
        pk.y = cvt_f16x2(v.w, v.z);
        *(uint2*)(smc + EP_WOFF + SWZ((uint32_t)(oc * 128 + c4 * 8))) = pk;
    }
    CP_WAIT_ALL();
    __syncthreads();

    const int t = lid >> 3, r = lid & 7;
    const int rowsel = (t & 1) * 8 + r;
    const int khalf16 = (t >> 1) * 16;
    const int posg = wid >> 2, ocg = wid & 3;
    const int pos0 = posg * 64, oc0 = ocg * 32;

    float acc[2][8][4];
    #pragma unroll
    for (int mt = 0; mt < 2; mt++)
        #pragma unroll
        for (int nt = 0; nt < 8; nt++)
            #pragma unroll
            for (int e = 0; e < 4; e++) acc[mt][nt][e] = 0.0f;

    #pragma unroll
    for (int ks = 0; ks < 4; ks++) {
        uint32_t a0[4], a1[4];
        LDSM_X4(a0, sb + EP_WOFF + SWZ((uint32_t)((oc0 + rowsel) * 128 + ks * 32 + khalf16)));
        LDSM_X4(a1, sb + EP_WOFF + SWZ((uint32_t)((oc0 + 16 + rowsel) * 128 + ks * 32 + khalf16)));
        #pragma unroll
        for (int nt4 = 0; nt4 < 4; nt4++) {
            uint32_t bfr[4];
            LDSM_X4(bfr, sb + EP_OOFF +
                    SWZ((uint32_t)((pos0 + nt4 * 16 + rowsel) * 128 + ks * 32 + khalf16)));
            MMA_F16_ACC(acc[0][2 * nt4],     a0, bfr[0], bfr[2]);
            MMA_F16_ACC(acc[0][2 * nt4 + 1], a0, bfr[1], bfr[3]);
            MMA_F16_ACC(acc[1][2 * nt4],     a1, bfr[0], bfr[2]);
            MMA_F16_ACC(acc[1][2 * nt4 + 1], a1, bfr[1], bfr[3]);
        }
    }
    __syncthreads();

    const float gamma = __ldg(gptr);
    const int g = lid >> 2, tc = lid & 3;
    #pragma unroll
    for (int mt = 0; mt < 2; mt++) {
        int row0 = oc0 + mt * 16 + g;
        #pragma unroll
        for (int nt = 0; nt < 8; nt++) {
            int colb = (pos0 + nt * 8 + tc * 2) * 2;
            uint32_t lo = cvt_f16x2(gamma * acc[mt][nt][1], gamma * acc[mt][nt][0]);
            uint32_t hi = cvt_f16x2(gamma * acc[mt][nt][3], gamma * acc[mt][nt][2]);
            *(uint32_t*)(smc + EP_RB + row0 * 272 + colb)       = lo;
            *(uint32_t*)(smc + EP_RB + (row0 + 8) * 272 + colb) = hi;
        }
    }
    __syncthreads();

    #pragma unroll 4
    for (int i = tid; i < 4096; i += 256) {
        int oc = i >> 5, ch = i & 31;
        uint2 pk = *(const uint2*)(smc + EP_RB + oc * 272 + ch * 8);
        float2 f0 = __half22float2(*(__half2*)&pk.x);
        float2 f1 = __half22float2(*(__half2*)&pk.y);
        size_t off = ((size_t)(b * CC) + oc) * HWV + i0 + ch * 4;
        float4 xv = *(const float4*)(x + off);
        float4 w;
        w.x = xv.x + f0.x; w.y = xv.y + f0.y;
        w.z = xv.z + f1.x; w.w = xv.w + f1.y;
        *(float4*)(out + off) = w;
    }
}

// ---------------------------------------------------------------------------
extern "C" void kernel_launch(void* const* d_in, const int* in_sizes, int n_in,
                              void* d_out, int out_size)
{
    const float* x   = (const float*)d_in[0];
    const float* wth = (const float*)d_in[1];
    const float* wph = (const float*)d_in[2];
    const float* wg  = (const float*)d_in[3];
    const float* wo  = (const float*)d_in[4];
    const float* gmm = (const float*)d_in[5];
    float* out = (float*)d_out;

    const int SMEM_A = CV_SMEM;                    // 221216
    const int SMEM_B = 8192 + 32768 + 131072;      // 172032
    const int SMEM_C = EP_SMEM;                    // 34816

    cudaFuncSetAttribute(convpool_kernel, cudaFuncAttributeMaxDynamicSharedMemorySize, SMEM_A);
    cudaFuncSetAttribute(attn_kernel,     cudaFuncAttributeMaxDynamicSharedMemorySize, SMEM_B);
    cudaFuncSetAttribute(epilogue_kernel, cudaFuncAttributeMaxDynamicSharedMemorySize, SMEM_C);

    convpool_kernel<<<dim3(16, 8), 512, SMEM_A>>>(x, wth, wph, wg);
    attn_kernel<<<dim3(16, 8), 256, SMEM_B>>>();
    epilogue_kernel<<<dim3(32, 8), 256, SMEM_C>>>(x, wo, gmm, out);
}